// round 6
// baseline (speedup 1.0000x reference)
#include <cuda_runtime.h>
#include <cuda_bf16.h>
#include <cstdint>

// out[M,N] = x[M,K] @ W[N,K]^T + bias ; M=8192, N=4096, K=1024 (fp32)
// bf16x3 split GEMM on mma.sync HMMA. Round 6: 2 CTAs/SM (256thr, 128x128 tile,
// 2 stages) so one CTA's barriers are covered by the other's MMA stream.

#define MDIM 8192
#define NDIM 4096
#define KDIM 1024

#define BM 128
#define BN 128
#define BK 32
#define STAGES 2
#define NCHUNK (KDIM / BK)      // 32

#define ROWB 80                 // padded smem row: 32 bf16 = 64B + 16B pad
#define OFF_AH 0
#define OFF_AL (128 * ROWB)     // 10240
#define OFF_BH (256 * ROWB)     // 20480
#define OFF_BL (384 * ROWB)     // 30720
#define STAGEB (512 * ROWB)     // 40960
#define SMEM_TOTAL (STAGES * STAGEB)  // 81920 per CTA -> 2 CTAs = 163840/SM

// ---- static scratch for split operands ----
__device__ __align__(256) __nv_bfloat16 g_Ah[MDIM * KDIM];
__device__ __align__(256) __nv_bfloat16 g_Al[MDIM * KDIM];
__device__ __align__(256) __nv_bfloat16 g_Bh[NDIM * KDIM];
__device__ __align__(256) __nv_bfloat16 g_Bl[NDIM * KDIM];

// ================= PTX helpers (base PTX only) =================
__device__ __forceinline__ uint32_t smem_u32(const void* p) {
    uint32_t a;
    asm("{ .reg .u64 t; cvta.to.shared.u64 t, %1; cvt.u32.u64 %0, t; }" : "=r"(a) : "l"(p));
    return a;
}
__device__ __forceinline__ void cp16(uint32_t dst, const void* src) {
    asm volatile("cp.async.cg.shared.global [%0], [%1], 16;" :: "r"(dst), "l"(src));
}
#define CP_COMMIT() asm volatile("cp.async.commit_group;" ::: "memory")
#define CP_WAIT1()  asm volatile("cp.async.wait_group 1;"  ::: "memory")
#define CP_WAIT0()  asm volatile("cp.async.wait_group 0;"  ::: "memory")

__device__ __forceinline__ void ldm_x4(uint32_t* r, uint32_t addr) {
    asm volatile("ldmatrix.sync.aligned.m8n8.x4.shared.b16 {%0,%1,%2,%3}, [%4];"
        : "=r"(r[0]), "=r"(r[1]), "=r"(r[2]), "=r"(r[3]) : "r"(addr));
}
__device__ __forceinline__ void mma16816(float* d, const uint32_t* a, const uint32_t* b) {
    asm volatile("mma.sync.aligned.m16n8k16.row.col.f32.bf16.bf16.f32 "
        "{%0,%1,%2,%3}, {%4,%5,%6,%7}, {%8,%9}, {%0,%1,%2,%3};"
        : "+f"(d[0]), "+f"(d[1]), "+f"(d[2]), "+f"(d[3])
        : "r"(a[0]), "r"(a[1]), "r"(a[2]), "r"(a[3]), "r"(b[0]), "r"(b[1]));
}

// ================= merged split kernel: fp32 -> (bf16 hi, bf16 lo) =================
__global__ void split_both_kernel(const float* __restrict__ srcA,
                                  const float* __restrict__ srcB,
                                  __nv_bfloat16* __restrict__ hiA, __nv_bfloat16* __restrict__ loA,
                                  __nv_bfloat16* __restrict__ hiB, __nv_bfloat16* __restrict__ loB,
                                  int n4a, int n4tot)
{
    int i = blockIdx.x * blockDim.x + threadIdx.x;
    if (i >= n4tot) return;
    const float* src;
    __nv_bfloat16 *hi, *lo;
    int idx;
    if (i < n4a) { src = srcA; hi = hiA; lo = loA; idx = i; }
    else         { src = srcB; hi = hiB; lo = loB; idx = i - n4a; }

    float4 v = reinterpret_cast<const float4*>(src)[idx];
    float vs[4] = {v.x, v.y, v.z, v.w};
    unsigned short hs[4], ls[4];
    #pragma unroll
    for (int j = 0; j < 4; j++) {
        __nv_bfloat16 h = __float2bfloat16(vs[j]);
        __nv_bfloat16 l = __float2bfloat16(vs[j] - __bfloat162float(h));
        hs[j] = ((__nv_bfloat16_raw)h).x;
        ls[j] = ((__nv_bfloat16_raw)l).x;
    }
    ushort4 ho = {hs[0], hs[1], hs[2], hs[3]};
    ushort4 lv = {ls[0], ls[1], ls[2], ls[3]};
    reinterpret_cast<ushort4*>(hi)[idx] = ho;
    reinterpret_cast<ushort4*>(lo)[idx] = lv;
}

// ================= main GEMM kernel =================
__global__ void __launch_bounds__(256, 2)
qgemm_mma(const __nv_bfloat16* __restrict__ Ah, const __nv_bfloat16* __restrict__ Al,
          const __nv_bfloat16* __restrict__ Bh, const __nv_bfloat16* __restrict__ Bl,
          const float* __restrict__ bias, float* __restrict__ C)
{
    extern __shared__ char smem[];
    const uint32_t sbase = smem_u32(smem);
    const int tid  = threadIdx.x;
    const int wid  = tid >> 5;
    const int lane = tid & 31;
    const int bm = blockIdx.y * BM;
    const int bn = blockIdx.x * BN;
    const int wm = (wid >> 2) * 64;   // warp row offset (0 or 64)
    const int wn = (wid & 3) * 32;    // warp col offset (0..96)

    // cp.async coords: 256 threads, each copies 8 x 16B per stage
    const int lrow = tid >> 2;        // 0..63
    const int lc   = tid & 3;

    float acc[4][4][4];
    #pragma unroll
    for (int i = 0; i < 4; i++)
        #pragma unroll
        for (int j = 0; j < 4; j++)
            #pragma unroll
            for (int k = 0; k < 4; k++)
                acc[i][j][k] = 0.0f;

    auto issue_stage = [&](int chunk, int stage) {
        const uint32_t sst = sbase + stage * STAGEB;
        const size_t kbyte = (size_t)chunk * (BK * 2) + lc * 16;
        const uint32_t dst = sst + lrow * ROWB + lc * 16;
        const size_t rowa0 = (size_t)(bm + lrow) * (KDIM * 2) + kbyte;
        const size_t rowa1 = (size_t)(bm + 64 + lrow) * (KDIM * 2) + kbyte;
        const size_t rowb0 = (size_t)(bn + lrow) * (KDIM * 2) + kbyte;
        const size_t rowb1 = (size_t)(bn + 64 + lrow) * (KDIM * 2) + kbyte;
        cp16(dst,                       (const char*)Ah + rowa0);
        cp16(dst + 64 * ROWB,           (const char*)Ah + rowa1);
        cp16(dst + OFF_AL,              (const char*)Al + rowa0);
        cp16(dst + OFF_AL + 64 * ROWB,  (const char*)Al + rowa1);
        cp16(dst + OFF_BH,              (const char*)Bh + rowb0);
        cp16(dst + OFF_BH + 64 * ROWB,  (const char*)Bh + rowb1);
        cp16(dst + OFF_BL,              (const char*)Bl + rowb0);
        cp16(dst + OFF_BL + 64 * ROWB,  (const char*)Bl + rowb1);
        CP_COMMIT();
    };

    issue_stage(0, 0);
    issue_stage(1, 1);

    // ldmatrix lane addressing
    const uint32_t a_off = (uint32_t)(wm + (lane & 15)) * ROWB + ((uint32_t)(lane >> 4)) * 16;
    const uint32_t b_off = OFF_BH +
        (uint32_t)(wn + (lane & 7) + ((lane >> 4) & 1) * 8) * ROWB +
        ((uint32_t)((lane >> 3) & 1)) * 16;

    for (int c = 0; c < NCHUNK; c++) {
        CP_WAIT1();              // chunk c landed
        __syncthreads();

        const uint32_t sst = sbase + (c & 1) * STAGEB;
        #pragma unroll
        for (int ks = 0; ks < 2; ks++) {
            uint32_t bh[4][2], bl[4][2];
            #pragma unroll
            for (int p = 0; p < 2; p++) {
                uint32_t r[4];
                uint32_t addr = sst + b_off + p * (16 * ROWB) + ks * 32;
                ldm_x4(r, addr);
                bh[p*2][0] = r[0]; bh[p*2][1] = r[1];
                bh[p*2+1][0] = r[2]; bh[p*2+1][1] = r[3];
                ldm_x4(r, addr + (OFF_BL - OFF_BH));
                bl[p*2][0] = r[0]; bl[p*2][1] = r[1];
                bl[p*2+1][0] = r[2]; bl[p*2+1][1] = r[3];
            }
            #pragma unroll
            for (int mb = 0; mb < 4; mb++) {
                uint32_t ah[4], al[4];
                uint32_t addr = sst + a_off + mb * (16 * ROWB) + ks * 32;
                ldm_x4(ah, addr);
                ldm_x4(al, addr + OFF_AL);
                #pragma unroll
                for (int nb = 0; nb < 4; nb++)
                    mma16816(acc[mb][nb], ah, bh[nb]);
                #pragma unroll
                for (int nb = 0; nb < 4; nb++)
                    mma16816(acc[mb][nb], ah, bl[nb]);
                #pragma unroll
                for (int nb = 0; nb < 4; nb++)
                    mma16816(acc[mb][nb], al, bh[nb]);
            }
        }

        __syncthreads();         // all warps done reading stage (c&1)
        if (c + 2 < NCHUNK) issue_stage(c + 2, c & 1);
    }
    CP_WAIT0();

    // -------- epilogue: + bias, store --------
    const int g  = lane >> 2;
    const int tg = lane & 3;
    #pragma unroll
    for (int mb = 0; mb < 4; mb++) {
        #pragma unroll
        for (int nb = 0; nb < 4; nb++) {
            const int col = bn + wn + nb * 8 + tg * 2;
            const float2 bv = *reinterpret_cast<const float2*>(bias + col);
            const int r0 = bm + wm + mb * 16 + g;
            float2 o0 = {acc[mb][nb][0] + bv.x, acc[mb][nb][1] + bv.y};
            float2 o1 = {acc[mb][nb][2] + bv.x, acc[mb][nb][3] + bv.y};
            *reinterpret_cast<float2*>(C + (size_t)r0 * NDIM + col) = o0;
            *reinterpret_cast<float2*>(C + (size_t)(r0 + 8) * NDIM + col) = o1;
        }
    }
}

// ================= host side =================
extern "C" void kernel_launch(void* const* d_in, const int* in_sizes, int n_in,
                              void* d_out, int out_size)
{
    const float* x    = (const float*)d_in[0];   // [M, K]
    const float* w    = (const float*)d_in[1];   // [N, K]
    const float* bias = (const float*)d_in[2];   // [N]
    float* out        = (float*)d_out;           // [M, N]

    void *pAh, *pAl, *pBh, *pBl;
    cudaGetSymbolAddress(&pAh, g_Ah);
    cudaGetSymbolAddress(&pAl, g_Al);
    cudaGetSymbolAddress(&pBh, g_Bh);
    cudaGetSymbolAddress(&pBl, g_Bl);

    int n4a = MDIM * KDIM / 4;
    int n4b = NDIM * KDIM / 4;
    int n4tot = n4a + n4b;
    split_both_kernel<<<(n4tot + 255) / 256, 256>>>(
        x, w,
        (__nv_bfloat16*)pAh, (__nv_bfloat16*)pAl,
        (__nv_bfloat16*)pBh, (__nv_bfloat16*)pBl, n4a, n4tot);

    static bool attr_set = false;
    if (!attr_set) {
        cudaFuncSetAttribute(qgemm_mma, cudaFuncAttributeMaxDynamicSharedMemorySize, SMEM_TOTAL);
        attr_set = true;
    }
    dim3 grid(NDIM / BN, MDIM / BM);   // (32, 64) = 2048 CTAs
    qgemm_mma<<<grid, 256, SMEM_TOTAL>>>((const __nv_bfloat16*)pAh, (const __nv_bfloat16*)pAl,
                                         (const __nv_bfloat16*)pBh, (const __nv_bfloat16*)pBl,
                                         bias, out);
}